// round 4
// baseline (speedup 1.0000x reference)
#include <cuda_runtime.h>
#include <cuda_bf16.h>
#include <cstdint>

// Problem constants
#define BATCH   4
#define TSEQ    2048
#define CDIM    1024
#define NHEAD   16
#define HDIM    64
#define FDIM    4096
#define MROWS   (BATCH * TSEQ)          // 8192
#define QKVDIM  (3 * CDIM)              // 3072
#define SM_SCALE 0.03125f               // C^-0.5 = 1/32

// ---------------- scratch (static device globals; no allocation) ----------------
__device__ float g_h   [MROWS * CDIM];    // LN output (tf32 bits)
__device__ float g_qkv [MROWS * QKVDIM];  // [M, 3C]: q | k | v (tf32 bits)
__device__ float g_attn[MROWS * CDIM];    // attention out (tf32 bits)
__device__ float g_x1  [MROWS * CDIM];    // x + attn@Wp + bp (fp32, residual)
__device__ float g_ff  [MROWS * FDIM];    // relu(h@W1+b1) (tf32 bits)
__device__ float g_wqkv[CDIM * QKVDIM];   // packed [C, 3C] (tf32 bits)
__device__ float g_wpc [CDIM * CDIM];     // Wp (tf32 bits)
__device__ float g_w1c [CDIM * FDIM];     // W1 (tf32 bits)
__device__ float g_w2c [FDIM * CDIM];     // W2 (tf32 bits)

// ---------------- helpers ----------------
__device__ __forceinline__ uint32_t tf32c(float x) {
    uint32_t r;
    asm("cvt.rna.tf32.f32 %0, %1;" : "=r"(r) : "f"(x));
    return r;
}
__device__ __forceinline__ float tf32f(float x) {
    return __uint_as_float(tf32c(x));
}
__device__ __forceinline__ void cp16(void* smem, const void* gsrc) {
    uint32_t s = (uint32_t)__cvta_generic_to_shared(smem);
    asm volatile("cp.async.cg.shared.global [%0], [%1], 16;\n" :: "r"(s), "l"(gsrc));
}
__device__ __forceinline__ void mma_tf32(float* c, const uint32_t* a, const uint32_t* b) {
    asm volatile(
        "mma.sync.aligned.m16n8k8.row.col.f32.tf32.tf32.f32 "
        "{%0,%1,%2,%3}, {%4,%5,%6,%7}, {%8,%9}, {%0,%1,%2,%3};\n"
        : "+f"(c[0]), "+f"(c[1]), "+f"(c[2]), "+f"(c[3])
        : "r"(a[0]), "r"(a[1]), "r"(a[2]), "r"(a[3]), "r"(b[0]), "r"(b[1]));
}

// ---------------- pack Wq/Wk/Wv from [H,C,D] into [C, 3C], tf32-rounded ----------------
__global__ void pack_w_kernel(const float* __restrict__ Wq, const float* __restrict__ Wk,
                              const float* __restrict__ Wv) {
    int idx = blockIdx.x * 256 + threadIdx.x;   // over C*C = 1M
    int h = idx >> 16;
    int c = (idx >> 6) & 1023;
    int d = idx & 63;
    int o = c * QKVDIM + h * HDIM + d;
    g_wqkv[o]            = tf32f(Wq[idx]);
    g_wqkv[o + CDIM]     = tf32f(Wk[idx]);
    g_wqkv[o + 2 * CDIM] = tf32f(Wv[idx]);
}

// ---------------- tf32 conversion pass for raw weights ----------------
__global__ void cvt_tf32_kernel(const float* __restrict__ src, float* __restrict__ dst) {
    int i = (blockIdx.x * 256 + threadIdx.x) * 4;
    float4 v = *(const float4*)(src + i);
    v.x = tf32f(v.x); v.y = tf32f(v.y); v.z = tf32f(v.z); v.w = tf32f(v.w);
    *(float4*)(dst + i) = v;
}

// ---------------- layernorm (output tf32-rounded: feeds GEMM A) ----------------
__global__ void layernorm_kernel(const float* __restrict__ x, const float* __restrict__ g,
                                 const float* __restrict__ b, float* __restrict__ out) {
    const int row = blockIdx.x;
    const int t = threadIdx.x;
    const size_t off = (size_t)row * CDIM + t * 4;
    float4 v = *(const float4*)(x + off);
    float s  = v.x + v.y + v.z + v.w;
    float ss = fmaf(v.x, v.x, fmaf(v.y, v.y, fmaf(v.z, v.z, v.w * v.w)));
#pragma unroll
    for (int o = 16; o; o >>= 1) {
        s  += __shfl_xor_sync(0xffffffffu, s,  o);
        ss += __shfl_xor_sync(0xffffffffu, ss, o);
    }
    __shared__ float ws[8], wss[8];
    __shared__ float s_mu, s_rs;
    int lane = t & 31, wid = t >> 5;
    if (lane == 0) { ws[wid] = s; wss[wid] = ss; }
    __syncthreads();
    if (t == 0) {
        float S = 0.f, SS = 0.f;
#pragma unroll
        for (int i = 0; i < 8; ++i) { S += ws[i]; SS += wss[i]; }
        float mu  = S * (1.f / CDIM);
        float var = SS * (1.f / CDIM) - mu * mu;
        s_mu = mu;
        s_rs = rsqrtf(var + 1e-5f);
    }
    __syncthreads();
    float mu = s_mu, rs = s_rs;
    float4 gv = *(const float4*)(g + t * 4);
    float4 bv = *(const float4*)(b + t * 4);
    float4 ov;
    ov.x = tf32f((v.x - mu) * rs * gv.x + bv.x);
    ov.y = tf32f((v.y - mu) * rs * gv.y + bv.y);
    ov.z = tf32f((v.z - mu) * rs * gv.z + bv.z);
    ov.w = tf32f((v.w - mu) * rs * gv.w + bv.w);
    *(float4*)(out + off) = ov;
}

// ---------------- TF32 tensor-core GEMM (inputs pre-converted; no cvt in loop) ----------------
// EPI: 0 = none, 2 = bias+relu, 3 = bias+residual.  CVTOUT: round result to tf32 at store.
#define AS_STRIDE 20
#define BS_STRIDE 136

template <int EPI, bool CVTOUT>
__global__ __launch_bounds__(256, 2)
void tf32gemm_kernel(const float* __restrict__ A, const float* __restrict__ Bm,
                     float* __restrict__ Cm, const float* __restrict__ bias,
                     const float* __restrict__ res, int M, int N, int K) {
    __shared__ float As[2][128][AS_STRIDE];
    __shared__ float Bs[2][16][BS_STRIDE];

    const int tid  = threadIdx.x;
    const int lane = tid & 31, wid = tid >> 5;
    const int warpM = wid & 1;
    const int warpN = wid >> 1;
    const int row0 = blockIdx.y * 128, col0 = blockIdx.x * 128;
    const int g  = lane >> 2;
    const int tg = lane & 3;

    const int arow = tid >> 2, ac4 = (tid & 3) * 4;
    const int bkr  = tid >> 5, bn4 = (tid & 31) * 4;

    float acc[4][4][4];
#pragma unroll
    for (int mt = 0; mt < 4; ++mt)
#pragma unroll
        for (int nt = 0; nt < 4; ++nt)
#pragma unroll
            for (int r = 0; r < 4; ++r) acc[mt][nt][r] = 0.f;

#define LOAD_STAGE(s, k0)                                                            \
    do {                                                                             \
        cp16(&As[s][arow][ac4],      A + (size_t)(row0 + arow) * K + (k0) + ac4);    \
        cp16(&As[s][arow + 64][ac4], A + (size_t)(row0 + arow + 64) * K + (k0) + ac4);\
        cp16(&Bs[s][bkr][bn4],       Bm + (size_t)((k0) + bkr) * N + col0 + bn4);    \
        cp16(&Bs[s][bkr + 8][bn4],   Bm + (size_t)((k0) + bkr + 8) * N + col0 + bn4);\
        asm volatile("cp.async.commit_group;\n");                                    \
    } while (0)

    LOAD_STAGE(0, 0);
    const int KT = K >> 4;
    for (int kt = 0; kt < KT; ++kt) {
        if (kt + 1 < KT) {
            LOAD_STAGE((kt + 1) & 1, (kt + 1) << 4);
            asm volatile("cp.async.wait_group 1;\n");
        } else {
            asm volatile("cp.async.wait_group 0;\n");
        }
        __syncthreads();
        const int s = kt & 1;
#pragma unroll
        for (int ch = 0; ch < 2; ++ch) {
            const int kc = ch * 8;
            uint32_t a[4][4], b[4][2];
#pragma unroll
            for (int mt = 0; mt < 4; ++mt) {
                const int r = warpM * 64 + mt * 16 + g;
                const int c = kc + tg;
                a[mt][0] = __float_as_uint(As[s][r][c]);
                a[mt][1] = __float_as_uint(As[s][r + 8][c]);
                a[mt][2] = __float_as_uint(As[s][r][c + 4]);
                a[mt][3] = __float_as_uint(As[s][r + 8][c + 4]);
            }
#pragma unroll
            for (int nt = 0; nt < 4; ++nt) {
                const int n = warpN * 32 + nt * 8 + g;
                const int k = kc + tg;
                b[nt][0] = __float_as_uint(Bs[s][k][n]);
                b[nt][1] = __float_as_uint(Bs[s][k + 4][n]);
            }
#pragma unroll
            for (int mt = 0; mt < 4; ++mt)
#pragma unroll
                for (int nt = 0; nt < 4; ++nt)
                    mma_tf32(acc[mt][nt], a[mt], b[nt]);
        }
        __syncthreads();
    }
#undef LOAD_STAGE

#pragma unroll
    for (int mt = 0; mt < 4; ++mt) {
#pragma unroll
        for (int nt = 0; nt < 4; ++nt) {
            const int r = row0 + warpM * 64 + mt * 16 + g;
            const int c = col0 + warpN * 32 + nt * 8 + 2 * tg;
            float2 v0 = make_float2(acc[mt][nt][0], acc[mt][nt][1]);
            float2 v1 = make_float2(acc[mt][nt][2], acc[mt][nt][3]);
            if (EPI >= 2) {
                float b0 = bias[c], b1 = bias[c + 1];
                v0.x += b0; v0.y += b1;
                v1.x += b0; v1.y += b1;
            }
            if (EPI == 2) {
                v0.x = fmaxf(v0.x, 0.f); v0.y = fmaxf(v0.y, 0.f);
                v1.x = fmaxf(v1.x, 0.f); v1.y = fmaxf(v1.y, 0.f);
            }
            if (EPI == 3) {
                float2 r0 = *(const float2*)(res + (size_t)r * N + c);
                float2 r1 = *(const float2*)(res + (size_t)(r + 8) * N + c);
                v0.x += r0.x; v0.y += r0.y;
                v1.x += r1.x; v1.y += r1.y;
            }
            if (CVTOUT) {
                v0.x = tf32f(v0.x); v0.y = tf32f(v0.y);
                v1.x = tf32f(v1.x); v1.y = tf32f(v1.y);
            }
            *(float2*)(Cm + (size_t)r * N + c)       = v0;
            *(float2*)(Cm + (size_t)(r + 8) * N + c) = v1;
        }
    }
}

// ---------------- tensor-core flash attention (TF32 mma), causal ----------------
// Q/K/V arrive pre-rounded to tf32 -> no cvt in mainloop (only on P/exp output).
#define PS_STR 68
#define KS_STR 76
#define VS_STR 72
#define FA_SMEM ((64 * PS_STR + 64 * KS_STR + 64 * VS_STR) * 4)

__global__ __launch_bounds__(128)
void flash_attn_tc_kernel(const float* __restrict__ QKV, float* __restrict__ O) {
    extern __shared__ float sm[];
    float* Ps = sm;                              // [64][68] (also Q staging)
    float* Ks = sm + 64 * PS_STR;                // [64][76]
    float* Vs = sm + 64 * PS_STR + 64 * KS_STR;  // [64][72]

    const int qb = blockIdx.x, h = blockIdx.y, b = blockIdx.z;
    const int tid = threadIdx.x, lane = tid & 31, w = tid >> 5;
    const int g = lane >> 2, tg = lane & 3;
    const int q0 = qb * 64;
    const int mrow = w * 16;
    const size_t base  = (size_t)b * TSEQ * QKVDIM + h * HDIM;
    const size_t obase = (size_t)b * TSEQ * CDIM + h * HDIM;
    const float* Q = QKV;
    const float* K = QKV + CDIM;
    const float* V = QKV + 2 * CDIM;

    // stage Q tile, extract fragments (already tf32 bits)
    for (int i = tid; i < 64 * 16; i += 128) {
        int r = i >> 4, c4 = (i & 15) * 4;
        float4 qv = *(const float4*)(Q + base + (size_t)(q0 + r) * QKVDIM + c4);
        float* dst = Ps + r * PS_STR + c4;
        dst[0] = qv.x; dst[1] = qv.y; dst[2] = qv.z; dst[3] = qv.w;
    }
    __syncthreads();
    uint32_t qf[8][4];
#pragma unroll
    for (int kc = 0; kc < 8; ++kc) {
        const int c = kc * 8;
        qf[kc][0] = __float_as_uint(Ps[(mrow + g)     * PS_STR + c + tg]);
        qf[kc][1] = __float_as_uint(Ps[(mrow + g + 8) * PS_STR + c + tg]);
        qf[kc][2] = __float_as_uint(Ps[(mrow + g)     * PS_STR + c + tg + 4]);
        qf[kc][3] = __float_as_uint(Ps[(mrow + g + 8) * PS_STR + c + tg + 4]);
    }
    __syncthreads();

    float oacc[8][4];
#pragma unroll
    for (int n = 0; n < 8; ++n)
#pragma unroll
        for (int r = 0; r < 4; ++r) oacc[n][r] = 0.f;
    float m0 = -1e30f, m1 = -1e30f, l0 = 0.f, l1 = 0.f;

    for (int j = 0; j <= qb; ++j) {
        const int k0 = j * 64;
        for (int i = tid; i < 64 * 16; i += 128) {
            int r = i >> 4, c4 = (i & 15) * 4;
            float4 kv = *(const float4*)(K + base + (size_t)(k0 + r) * QKVDIM + c4);
            float* kd = Ks + r * KS_STR + c4;
            kd[0] = kv.x; kd[1] = kv.y; kd[2] = kv.z; kd[3] = kv.w;
            float4 vv = *(const float4*)(V + base + (size_t)(k0 + r) * QKVDIM + c4);
            float* vd = Vs + r * VS_STR + c4;
            vd[0] = vv.x; vd[1] = vv.y; vd[2] = vv.z; vd[3] = vv.w;
        }
        __syncthreads();

        // ---- S = Q K^T ----
        float sacc[8][4];
#pragma unroll
        for (int n = 0; n < 8; ++n) {
#pragma unroll
            for (int r = 0; r < 4; ++r) sacc[n][r] = 0.f;
        }
#pragma unroll
        for (int n = 0; n < 8; ++n) {
            const float* krow = Ks + (n * 8 + g) * KS_STR;
#pragma unroll
            for (int kc = 0; kc < 8; ++kc) {
                uint32_t bb[2];
                bb[0] = __float_as_uint(krow[kc * 8 + tg]);
                bb[1] = __float_as_uint(krow[kc * 8 + tg + 4]);
                mma_tf32(sacc[n], qf[kc], bb);
            }
        }

        // ---- online softmax ----
        const bool diag = (j == qb);
#pragma unroll
        for (int n = 0; n < 8; ++n) {
            sacc[n][0] *= SM_SCALE; sacc[n][1] *= SM_SCALE;
            sacc[n][2] *= SM_SCALE; sacc[n][3] *= SM_SCALE;
            if (diag) {
                const int c0 = n * 8 + 2 * tg, c1 = c0 + 1;
                const int r0 = mrow + g, r1 = r0 + 8;
                if (c0 > r0) sacc[n][0] = -1e30f;
                if (c1 > r0) sacc[n][1] = -1e30f;
                if (c0 > r1) sacc[n][2] = -1e30f;
                if (c1 > r1) sacc[n][3] = -1e30f;
            }
        }
        float mx0 = -1e30f, mx1 = -1e30f;
#pragma unroll
        for (int n = 0; n < 8; ++n) {
            mx0 = fmaxf(mx0, fmaxf(sacc[n][0], sacc[n][1]));
            mx1 = fmaxf(mx1, fmaxf(sacc[n][2], sacc[n][3]));
        }
        mx0 = fmaxf(mx0, __shfl_xor_sync(0xffffffffu, mx0, 1));
        mx0 = fmaxf(mx0, __shfl_xor_sync(0xffffffffu, mx0, 2));
        mx1 = fmaxf(mx1, __shfl_xor_sync(0xffffffffu, mx1, 1));
        mx1 = fmaxf(mx1, __shfl_xor_sync(0xffffffffu, mx1, 2));
        const float mn0 = fmaxf(m0, mx0), mn1 = fmaxf(m1, mx1);
        const float al0 = __expf(m0 - mn0), al1 = __expf(m1 - mn1);
        m0 = mn0; m1 = mn1;

        float sum0 = 0.f, sum1 = 0.f;
        float* prow0 = Ps + (mrow + g) * PS_STR;
        float* prow1 = Ps + (mrow + g + 8) * PS_STR;
#pragma unroll
        for (int n = 0; n < 8; ++n) {
            float p00 = __expf(sacc[n][0] - mn0);
            float p01 = __expf(sacc[n][1] - mn0);
            float p10 = __expf(sacc[n][2] - mn1);
            float p11 = __expf(sacc[n][3] - mn1);
            sum0 += p00 + p01;
            sum1 += p10 + p11;
            const int c = n * 8 + 2 * tg;
            prow0[c]     = __uint_as_float(tf32c(p00));
            prow0[c + 1] = __uint_as_float(tf32c(p01));
            prow1[c]     = __uint_as_float(tf32c(p10));
            prow1[c + 1] = __uint_as_float(tf32c(p11));
        }
        sum0 += __shfl_xor_sync(0xffffffffu, sum0, 1);
        sum0 += __shfl_xor_sync(0xffffffffu, sum0, 2);
        sum1 += __shfl_xor_sync(0xffffffffu, sum1, 1);
        sum1 += __shfl_xor_sync(0xffffffffu, sum1, 2);
        l0 = l0 * al0 + sum0;
        l1 = l1 * al1 + sum1;
#pragma unroll
        for (int n = 0; n < 8; ++n) {
            oacc[n][0] *= al0; oacc[n][1] *= al0;
            oacc[n][2] *= al1; oacc[n][3] *= al1;
        }
        __syncwarp();

        // ---- O += P V ----
#pragma unroll
        for (int kc = 0; kc < 8; ++kc) {
            uint32_t aa[4];
            aa[0] = __float_as_uint(Ps[(mrow + g)     * PS_STR + kc * 8 + tg]);
            aa[1] = __float_as_uint(Ps[(mrow + g + 8) * PS_STR + kc * 8 + tg]);
            aa[2] = __float_as_uint(Ps[(mrow + g)     * PS_STR + kc * 8 + tg + 4]);
            aa[3] = __float_as_uint(Ps[(mrow + g + 8) * PS_STR + kc * 8 + tg + 4]);
            const float* v0 = Vs + (kc * 8 + tg) * VS_STR;
            const float* v1 = Vs + (kc * 8 + tg + 4) * VS_STR;
#pragma unroll
            for (int n = 0; n < 8; ++n) {
                uint32_t bb[2];
                bb[0] = __float_as_uint(v0[n * 8 + g]);
                bb[1] = __float_as_uint(v1[n * 8 + g]);
                mma_tf32(oacc[n], aa, bb);
            }
        }
        __syncthreads();
    }

    // store tf32-rounded (feeds proj GEMM A) — same rounding as round 3's in-GEMM cvt
    const float inv0 = 1.f / l0, inv1 = 1.f / l1;
    const int r0 = q0 + mrow + g, r1 = r0 + 8;
#pragma unroll
    for (int n = 0; n < 8; ++n) {
        const int c = n * 8 + 2 * tg;
        *(float2*)(O + obase + (size_t)r0 * CDIM + c) =
            make_float2(tf32f(oacc[n][0] * inv0), tf32f(oacc[n][1] * inv0));
        *(float2*)(O + obase + (size_t)r1 * CDIM + c) =
            make_float2(tf32f(oacc[n][2] * inv1), tf32f(oacc[n][3] * inv1));
    }
}

// ---------------- launch ----------------
extern "C" void kernel_launch(void* const* d_in, const int* in_sizes, int n_in,
                              void* d_out, int out_size) {
    (void)in_sizes; (void)n_in; (void)out_size;
    const float* x    = (const float*)d_in[0];
    const float* Wq   = (const float*)d_in[1];
    const float* Wk   = (const float*)d_in[2];
    const float* Wv   = (const float*)d_in[3];
    const float* Wp   = (const float*)d_in[4];
    const float* bp   = (const float*)d_in[5];
    const float* ln1g = (const float*)d_in[6];
    const float* ln1b = (const float*)d_in[7];
    const float* ln2g = (const float*)d_in[8];
    const float* ln2b = (const float*)d_in[9];
    const float* W1   = (const float*)d_in[10];
    const float* b1   = (const float*)d_in[11];
    const float* W2   = (const float*)d_in[12];
    const float* b2   = (const float*)d_in[13];
    float* out = (float*)d_out;

    float *h, *qkv, *attn, *x1, *ff, *wqkv, *wpc, *w1c, *w2c;
    cudaGetSymbolAddress((void**)&h,    g_h);
    cudaGetSymbolAddress((void**)&qkv,  g_qkv);
    cudaGetSymbolAddress((void**)&attn, g_attn);
    cudaGetSymbolAddress((void**)&x1,   g_x1);
    cudaGetSymbolAddress((void**)&ff,   g_ff);
    cudaGetSymbolAddress((void**)&wqkv, g_wqkv);
    cudaGetSymbolAddress((void**)&wpc,  g_wpc);
    cudaGetSymbolAddress((void**)&w1c,  g_w1c);
    cudaGetSymbolAddress((void**)&w2c,  g_w2c);

    // 0) weight conversions (tf32 bits)
    pack_w_kernel<<<(CDIM * CDIM) / 256, 256>>>(Wq, Wk, Wv);
    cvt_tf32_kernel<<<(CDIM * CDIM) / 1024, 256>>>(Wp, wpc);
    cvt_tf32_kernel<<<(CDIM * FDIM) / 1024, 256>>>(W1, w1c);
    cvt_tf32_kernel<<<(FDIM * CDIM) / 1024, 256>>>(W2, w2c);

    // 1) LN1 (tf32 out)
    layernorm_kernel<<<MROWS, 256>>>(x, ln1g, ln1b, h);

    // 2) fused QKV projection (tf32 out)
    tf32gemm_kernel<0, true><<<dim3(QKVDIM / 128, MROWS / 128), 256>>>(
        h, wqkv, qkv, nullptr, nullptr, MROWS, QKVDIM, CDIM);

    // 3) attention (tensor-core flash, tf32 out)
    cudaFuncSetAttribute(flash_attn_tc_kernel,
                         cudaFuncAttributeMaxDynamicSharedMemorySize, FA_SMEM);
    flash_attn_tc_kernel<<<dim3(TSEQ / 64, NHEAD, BATCH), 128, FA_SMEM>>>(qkv, attn);

    // 4) output projection + residual (fp32 out, residual-carried)
    tf32gemm_kernel<3, false><<<dim3(CDIM / 128, MROWS / 128), 256>>>(
        attn, wpc, x1, bp, x, MROWS, CDIM, CDIM);

    // 5) LN2 (tf32 out)
    layernorm_kernel<<<MROWS, 256>>>(x1, ln2g, ln2b, h);

    // 6) ff = relu(h@W1 + b1) (tf32 out)
    tf32gemm_kernel<2, true><<<dim3(FDIM / 128, MROWS / 128), 256>>>(
        h, w1c, ff, b1, nullptr, MROWS, FDIM, CDIM);

    // 7) out = x1 + ff@W2 + b2 (fp32 out)
    tf32gemm_kernel<3, false><<<dim3(CDIM / 128, MROWS / 128), 256>>>(
        ff, w2c, out, b2, x1, MROWS, CDIM, FDIM);
}

// round 6
// speedup vs baseline: 1.5351x; 1.5351x over previous
#include <cuda_runtime.h>
#include <cuda_fp16.h>
#include <cstdint>

// Problem constants
#define BATCH   4
#define TSEQ    2048
#define CDIM    1024
#define NHEAD   16
#define HDIM    64
#define FDIM    4096
#define MROWS   (BATCH * TSEQ)          // 8192
#define QKVDIM  (3 * CDIM)              // 3072
#define SM_SCALE 0.03125f               // C^-0.5 = 1/32

// ---------------- scratch (static device globals; no allocation) ----------------
__device__ __half g_h    [MROWS * CDIM];    // LN output
__device__ __half g_qkv  [MROWS * QKVDIM];  // q | k | v
__device__ __half g_attn [MROWS * CDIM];    // attention out
__device__ float  g_x1   [MROWS * CDIM];    // x + attn@Wp + bp (fp32 residual)
__device__ __half g_ff   [MROWS * FDIM];    // relu(h@W1+b1)
__device__ __half g_wqkvT[QKVDIM * CDIM];   // [3C, C] K-major
__device__ __half g_wpT  [CDIM * CDIM];     // Wp^T [C, C]
__device__ __half g_w1T  [FDIM * CDIM];     // W1^T [4C, C]
__device__ __half g_w2T  [CDIM * FDIM];     // W2^T [C, 4C]

// ---------------- helpers ----------------
__device__ __forceinline__ uint32_t tf32c(float x) {
    uint32_t r;
    asm("cvt.rna.tf32.f32 %0, %1;" : "=r"(r) : "f"(x));
    return r;
}
__device__ __forceinline__ uint32_t smem_u32(const void* p) {
    return (uint32_t)__cvta_generic_to_shared(p);
}
__device__ __forceinline__ void cp16s(uint32_t saddr, const void* gsrc) {
    asm volatile("cp.async.cg.shared.global [%0], [%1], 16;\n" :: "r"(saddr), "l"(gsrc));
}
__device__ __forceinline__ uint32_t lds32(const __half* p) {
    return *(const uint32_t*)p;
}
// fp16 mma: D(f32) += A(f16) B(f16), m16n8k16, row.col
__device__ __forceinline__ void mma_f16(float* c, const uint32_t* a, const uint32_t* b) {
    asm volatile(
        "mma.sync.aligned.m16n8k16.row.col.f32.f16.f16.f32 "
        "{%0,%1,%2,%3}, {%4,%5,%6,%7}, {%8,%9}, {%0,%1,%2,%3};\n"
        : "+f"(c[0]), "+f"(c[1]), "+f"(c[2]), "+f"(c[3])
        : "r"(a[0]), "r"(a[1]), "r"(a[2]), "r"(a[3]), "r"(b[0]), "r"(b[1]));
}
// tf32 mma for attention mainloop
__device__ __forceinline__ void mma_tf32(float* c, const uint32_t* a, const uint32_t* b) {
    asm volatile(
        "mma.sync.aligned.m16n8k8.row.col.f32.tf32.tf32.f32 "
        "{%0,%1,%2,%3}, {%4,%5,%6,%7}, {%8,%9}, {%0,%1,%2,%3};\n"
        : "+f"(c[0]), "+f"(c[1]), "+f"(c[2]), "+f"(c[3])
        : "r"(a[0]), "r"(a[1]), "r"(a[2]), "r"(a[3]), "r"(b[0]), "r"(b[1]));
}

// ---------------- weight transposes (fp16 out, K-major) ----------------
// Wq/Wk/Wv [H,C,D] -> g_wqkvT [3C, C]
__global__ void pack_wqkv_t_kernel(const float* __restrict__ Wq, const float* __restrict__ Wk,
                                   const float* __restrict__ Wv) {
    __shared__ float s[32][33];
    const int c0 = blockIdx.x * 32;
    const int n0 = blockIdx.y * 32;
    const float* W = (n0 < CDIM) ? Wq : (n0 < 2 * CDIM ? Wk : Wv);
    const int nloc = n0 & (CDIM - 1);
    const int h = nloc >> 6, d0 = nloc & 63;
    const int tx = threadIdx.x, ty = threadIdx.y;
#pragma unroll
    for (int i = ty; i < 32; i += 8)
        s[i][tx] = W[h * (CDIM * HDIM) + (c0 + i) * HDIM + d0 + tx];
    __syncthreads();
#pragma unroll
    for (int i = ty; i < 32; i += 8)
        g_wqkvT[(size_t)(n0 + i) * CDIM + c0 + tx] = __float2half_rn(s[tx][i]);
}

// generic [R,Cc] fp32 -> dst [Cc,R] fp16
__global__ void transpose_cvt_kernel(const float* __restrict__ src, __half* __restrict__ dst,
                                     int R, int Cc) {
    __shared__ float s[32][33];
    const int c0 = blockIdx.x * 32, r0 = blockIdx.y * 32;
    const int tx = threadIdx.x, ty = threadIdx.y;
#pragma unroll
    for (int i = ty; i < 32; i += 8)
        s[i][tx] = src[(size_t)(r0 + i) * Cc + c0 + tx];
    __syncthreads();
#pragma unroll
    for (int i = ty; i < 32; i += 8)
        dst[(size_t)(c0 + i) * R + r0 + tx] = __float2half_rn(s[tx][i]);
}

// ---------------- layernorm (fp16 output) ----------------
__global__ void layernorm_kernel(const float* __restrict__ x, const float* __restrict__ g,
                                 const float* __restrict__ b, __half* __restrict__ out) {
    const int row = blockIdx.x;
    const int t = threadIdx.x;
    const size_t off = (size_t)row * CDIM + t * 4;
    float4 v = *(const float4*)(x + off);
    float s  = v.x + v.y + v.z + v.w;
    float ss = fmaf(v.x, v.x, fmaf(v.y, v.y, fmaf(v.z, v.z, v.w * v.w)));
#pragma unroll
    for (int o = 16; o; o >>= 1) {
        s  += __shfl_xor_sync(0xffffffffu, s,  o);
        ss += __shfl_xor_sync(0xffffffffu, ss, o);
    }
    __shared__ float ws[8], wss[8];
    __shared__ float s_mu, s_rs;
    int lane = t & 31, wid = t >> 5;
    if (lane == 0) { ws[wid] = s; wss[wid] = ss; }
    __syncthreads();
    if (t == 0) {
        float S = 0.f, SS = 0.f;
#pragma unroll
        for (int i = 0; i < 8; ++i) { S += ws[i]; SS += wss[i]; }
        float mu  = S * (1.f / CDIM);
        float var = SS * (1.f / CDIM) - mu * mu;
        s_mu = mu;
        s_rs = rsqrtf(var + 1e-5f);
    }
    __syncthreads();
    float mu = s_mu, rs = s_rs;
    float4 gv = *(const float4*)(g + t * 4);
    float4 bv = *(const float4*)(b + t * 4);
    *(half2*)(out + off)     = __floats2half2_rn((v.x - mu) * rs * gv.x + bv.x,
                                                 (v.y - mu) * rs * gv.y + bv.y);
    *(half2*)(out + off + 2) = __floats2half2_rn((v.z - mu) * rs * gv.z + bv.z,
                                                 (v.w - mu) * rs * gv.w + bv.w);
}

// ---------------- fp16 tensor-core GEMM ----------------
// C[M,N] = A[M,K] @ Bt[N,K]^T.  128x128 tile, BK=32, 3-stage cp.async,
// 256 threads = 8 warps (2 x 4), warp tile 64x32, mma.m16n8k16.f16.
// EPI: 0 = none (half out), 2 = bias+relu (half out), 3 = bias+residual (float out)
#define HBK   32
#define HSTR  40                        // halves per smem row (conflict-free: bank=20g+tg)
#define HROWS 128
#define STAGE_H (2 * HROWS * HSTR)      // halves per stage (A then B)
#define H_SMEM  (3 * STAGE_H * 2)       // bytes

template <int EPI>
__global__ __launch_bounds__(256, 2)
void h16gemm_kernel(const __half* __restrict__ A, const __half* __restrict__ Bt,
                    void* __restrict__ Cv, const float* __restrict__ bias,
                    const float* __restrict__ res, int M, int N, int K) {
    extern __shared__ __half hsm[];
    const uint32_t sb = smem_u32(hsm);
    const int tid  = threadIdx.x;
    const int lane = tid & 31, wid = tid >> 5;
    const int warpM = wid & 1;          // 0..1 -> M offset 0/64
    const int warpN = wid >> 1;         // 0..3 -> N offset 0/32/64/96
    const int row0 = blockIdx.y * 128, col0 = blockIdx.x * 128;
    const int g  = lane >> 2;
    const int tg = lane & 3;
    const int KT = K / HBK;

    float acc[4][4][4];
#pragma unroll
    for (int mt = 0; mt < 4; ++mt)
#pragma unroll
        for (int nt = 0; nt < 4; ++nt)
#pragma unroll
            for (int r = 0; r < 4; ++r) acc[mt][nt][r] = 0.f;

    auto load_tile = [&](int kt, int st) {
        const uint32_t aoff = st * STAGE_H;
        const uint32_t boff = aoff + HROWS * HSTR;
        const size_t gk = (size_t)kt * HBK;
#pragma unroll
        for (int i = 0; i < 2; ++i) {
            int ch = tid + i * 256;            // 0..511
            int r = ch >> 2, c8 = (ch & 3) * 8;
            cp16s(sb + (aoff + r * HSTR + c8) * 2, A  + (size_t)(row0 + r) * K + gk + c8);
            cp16s(sb + (boff + r * HSTR + c8) * 2, Bt + (size_t)(col0 + r) * K + gk + c8);
        }
    };

    load_tile(0, 0);
    asm volatile("cp.async.commit_group;\n");
    load_tile(1, 1);
    asm volatile("cp.async.commit_group;\n");

    for (int t = 0; t < KT; ++t) {
        if (t + 2 < KT) {
            load_tile(t + 2, (t + 2) % 3);
            asm volatile("cp.async.commit_group;\n");
            asm volatile("cp.async.wait_group 2;\n");
        } else {
            asm volatile("cp.async.wait_group 0;\n");
        }
        __syncthreads();

        const __half* as = hsm + (t % 3) * STAGE_H;
        const __half* bs = as + HROWS * HSTR;
#pragma unroll
        for (int kc = 0; kc < 2; ++kc) {
            const int ko = kc * 16 + 2 * tg;
            uint32_t a[4][4], b[4][2];
#pragma unroll
            for (int mt = 0; mt < 4; ++mt) {
                const int r = warpM * 64 + mt * 16 + g;
                a[mt][0] = lds32(as + r * HSTR + ko);
                a[mt][1] = lds32(as + (r + 8) * HSTR + ko);
                a[mt][2] = lds32(as + r * HSTR + ko + 8);
                a[mt][3] = lds32(as + (r + 8) * HSTR + ko + 8);
            }
#pragma unroll
            for (int nt = 0; nt < 4; ++nt) {
                const int n = warpN * 32 + nt * 8 + g;
                b[nt][0] = lds32(bs + n * HSTR + ko);
                b[nt][1] = lds32(bs + n * HSTR + ko + 8);
            }
#pragma unroll
            for (int mt = 0; mt < 4; ++mt)
#pragma unroll
                for (int nt = 0; nt < 4; ++nt)
                    mma_f16(acc[mt][nt], a[mt], b[nt]);
        }
        __syncthreads();
    }

    // epilogue
#pragma unroll
    for (int mt = 0; mt < 4; ++mt) {
#pragma unroll
        for (int nt = 0; nt < 4; ++nt) {
            const int r = row0 + warpM * 64 + mt * 16 + g;
            const int c = col0 + warpN * 32 + nt * 8 + 2 * tg;
            float2 v0 = make_float2(acc[mt][nt][0], acc[mt][nt][1]);   // row r
            float2 v1 = make_float2(acc[mt][nt][2], acc[mt][nt][3]);   // row r+8
            if (EPI >= 2) {
                float b0 = bias[c], b1 = bias[c + 1];
                v0.x += b0; v0.y += b1;
                v1.x += b0; v1.y += b1;
            }
            if (EPI == 2) {
                v0.x = fmaxf(v0.x, 0.f); v0.y = fmaxf(v0.y, 0.f);
                v1.x = fmaxf(v1.x, 0.f); v1.y = fmaxf(v1.y, 0.f);
            }
            if (EPI == 3) {
                float2 r0 = *(const float2*)(res + (size_t)r * N + c);
                float2 r1 = *(const float2*)(res + (size_t)(r + 8) * N + c);
                v0.x += r0.x; v0.y += r0.y;
                v1.x += r1.x; v1.y += r1.y;
                float* Cf = (float*)Cv;
                *(float2*)(Cf + (size_t)r * N + c)       = v0;
                *(float2*)(Cf + (size_t)(r + 8) * N + c) = v1;
            } else {
                __half* Ch = (__half*)Cv;
                *(half2*)(Ch + (size_t)r * N + c)       = __floats2half2_rn(v0.x, v0.y);
                *(half2*)(Ch + (size_t)(r + 8) * N + c) = __floats2half2_rn(v1.x, v1.y);
            }
        }
    }
}

// ---------------- tensor-core flash attention (TF32 mma), causal ----------------
// QKV in fp16 (exactly representable in tf32); smem fp32; O in fp16.
#define PS_STR 68
#define KS_STR 76
#define VS_STR 72
#define FA_SMEM ((64 * PS_STR + 64 * KS_STR + 64 * VS_STR) * 4)

__global__ __launch_bounds__(128)
void flash_attn_tc_kernel(const __half* __restrict__ QKV, __half* __restrict__ O) {
    extern __shared__ float sm[];
    float* Ps = sm;                              // [64][68] (also Q staging)
    float* Ks = sm + 64 * PS_STR;                // [64][76]
    float* Vs = sm + 64 * PS_STR + 64 * KS_STR;  // [64][72]

    const int qb = blockIdx.x, h = blockIdx.y, b = blockIdx.z;
    const int tid = threadIdx.x, lane = tid & 31, w = tid >> 5;
    const int g = lane >> 2, tg = lane & 3;
    const int q0 = qb * 64;
    const int mrow = w * 16;
    const size_t base  = (size_t)b * TSEQ * QKVDIM + h * HDIM;
    const size_t obase = (size_t)b * TSEQ * CDIM + h * HDIM;
    const __half* Q = QKV;
    const __half* K = QKV + CDIM;
    const __half* V = QKV + 2 * CDIM;

    // stage Q tile (half -> fp32 smem)
    for (int i = tid; i < 512; i += 128) {
        int r = i >> 3, c8 = (i & 7) * 8;
        uint4 u = *(const uint4*)(Q + base + (size_t)(q0 + r) * QKVDIM + c8);
        const __half2* hp = (const __half2*)&u;
        float* dst = Ps + r * PS_STR + c8;
#pragma unroll
        for (int j = 0; j < 4; ++j) {
            float2 f = __half22float2(hp[j]);
            dst[2 * j] = f.x; dst[2 * j + 1] = f.y;
        }
    }
    __syncthreads();
    uint32_t qf[8][4];
#pragma unroll
    for (int kc = 0; kc < 8; ++kc) {
        const int c = kc * 8;
        qf[kc][0] = __float_as_uint(Ps[(mrow + g)     * PS_STR + c + tg]);
        qf[kc][1] = __float_as_uint(Ps[(mrow + g + 8) * PS_STR + c + tg]);
        qf[kc][2] = __float_as_uint(Ps[(mrow + g)     * PS_STR + c + tg + 4]);
        qf[kc][3] = __float_as_uint(Ps[(mrow + g + 8) * PS_STR + c + tg + 4]);
    }
    __syncthreads();

    float oacc[8][4];
#pragma unroll
    for (int n = 0; n < 8; ++n)
#pragma unroll
        for (int r = 0; r < 4; ++r) oacc[n][r] = 0.f;
    float m0 = -1e30f, m1 = -1e30f, l0 = 0.f, l1 = 0.f;

    for (int j = 0; j <= qb; ++j) {
        const int k0 = j * 64;
        for (int i = tid; i < 512; i += 128) {
            int r = i >> 3, c8 = (i & 7) * 8;
            uint4 uk = *(const uint4*)(K + base + (size_t)(k0 + r) * QKVDIM + c8);
            const __half2* hk = (const __half2*)&uk;
            float* kd = Ks + r * KS_STR + c8;
#pragma unroll
            for (int jj = 0; jj < 4; ++jj) {
                float2 f = __half22float2(hk[jj]);
                kd[2 * jj] = f.x; kd[2 * jj + 1] = f.y;
            }
            uint4 uv = *(const uint4*)(V + base + (size_t)(k0 + r) * QKVDIM + c8);
            const __half2* hv = (const __half2*)&uv;
            float* vd = Vs + r * VS_STR + c8;
#pragma unroll
            for (int jj = 0; jj < 4; ++jj) {
                float2 f = __half22float2(hv[jj]);
                vd[2 * jj] = f.x; vd[2 * jj + 1] = f.y;
            }
        }
        __syncthreads();

        // ---- S = Q K^T ----
        float sacc[8][4];
#pragma unroll
        for (int n = 0; n < 8; ++n)
#pragma unroll
            for (int r = 0; r < 4; ++r) sacc[n][r] = 0.f;
#pragma unroll
        for (int n = 0; n < 8; ++n) {
            const float* krow = Ks + (n * 8 + g) * KS_STR;
#pragma unroll
            for (int kc = 0; kc < 8; ++kc) {
                uint32_t bb[2];
                bb[0] = __float_as_uint(krow[kc * 8 + tg]);
                bb[1] = __float_as_uint(krow[kc * 8 + tg + 4]);
                mma_tf32(sacc[n], qf[kc], bb);
            }
        }

        // ---- online softmax ----
        const bool diag = (j == qb);
#pragma unroll
        for (int n = 0; n < 8; ++n) {
            sacc[n][0] *= SM_SCALE; sacc[n][1] *= SM_SCALE;
            sacc[n][2] *= SM_SCALE; sacc[n][3] *= SM_SCALE;
            if (diag) {
                const int c0 = n * 8 + 2 * tg, c1 = c0 + 1;
                const int r0 = mrow + g, r1 = r0 + 8;
                if (c0 > r0) sacc[n][0] = -1e30f;
                if (c1 > r0) sacc[n][1] = -1e30f;
                if (c0 > r1) sacc[n][2] = -1e30f;
                if (c1 > r1) sacc[n][3] = -1e30f;
            }
        }
        float mx0 = -1e30f, mx1 = -1e30f;
#pragma unroll
        for (int n = 0; n < 8; ++n) {
            mx0 = fmaxf(mx0, fmaxf(sacc[n][0], sacc[n][1]));
            mx1 = fmaxf(mx1, fmaxf(sacc[n][2], sacc[n][3]));
        }
        mx0 = fmaxf(mx0, __shfl_xor_sync(0xffffffffu, mx0, 1));
        mx0 = fmaxf(mx0, __shfl_xor_sync(0xffffffffu, mx0, 2));
        mx1 = fmaxf(mx1, __shfl_xor_sync(0xffffffffu, mx1, 1));
        mx1 = fmaxf(mx1, __shfl_xor_sync(0xffffffffu, mx1, 2));
        const float mn0 = fmaxf(m0, mx0), mn1 = fmaxf(m1, mx1);
        const float al0 = __expf(m0 - mn0), al1 = __expf(m1 - mn1);
        m0 = mn0; m1 = mn1;

        float sum0 = 0.f, sum1 = 0.f;
        float* prow0 = Ps + (mrow + g) * PS_STR;
        float* prow1 = Ps + (mrow + g + 8) * PS_STR;
#pragma unroll
        for (int n = 0; n < 8; ++n) {
            float p00 = __expf(sacc[n][0] - mn0);
            float p01 = __expf(sacc[n][1] - mn0);
            float p10 = __expf(sacc[n][2] - mn1);
            float p11 = __expf(sacc[n][3] - mn1);
            sum0 += p00 + p01;
            sum1 += p10 + p11;
            const int c = n * 8 + 2 * tg;
            prow0[c]     = __uint_as_float(tf32c(p00));
            prow0[c + 1] = __uint_as_float(tf32c(p01));
            prow1[c]     = __uint_as_float(tf32c(p10));
            prow1[c + 1] = __uint_as_float(tf32c(p11));
        }
        sum0 += __shfl_xor_sync(0xffffffffu, sum0, 1);
        sum0 += __shfl_xor_sync(0xffffffffu, sum0, 2);
        sum1 += __shfl_xor_sync(0xffffffffu, sum1, 1);
        sum1 += __shfl_xor_sync(0xffffffffu, sum1, 2);
        l0 = l0 * al0 + sum0;
        l1 = l1 * al1 + sum1;
#pragma unroll
        for (int n = 0; n < 8; ++n) {
            oacc[n][0] *= al0; oacc[n][1] *= al0;
            oacc[n][2] *= al1; oacc[n][3] *= al1;
        }
        __syncwarp();

        // ---- O += P V ----
#pragma unroll
        for (int kc = 0; kc < 8; ++kc) {
            uint32_t aa[4];
            aa[0] = __float_as_uint(Ps[(mrow + g)     * PS_STR + kc * 8 + tg]);
            aa[1] = __float_as_uint(Ps[(mrow + g + 8) * PS_STR + kc * 8 + tg]);
            aa[2] = __float_as_uint(Ps[(mrow + g)     * PS_STR + kc * 8 + tg + 4]);
            aa[3] = __float_as_uint(Ps[(mrow + g + 8) * PS_STR + kc * 8 + tg + 4]);
            const float* v0 = Vs + (kc * 8 + tg) * VS_STR;
            const float* v1 = Vs + (kc * 8 + tg + 4) * VS_STR;
#pragma unroll
            for (int n = 0; n < 8; ++n) {
                uint32_t bb[2];
                bb[0] = __float_as_uint(v0[n * 8 + g]);
                bb[1] = __float_as_uint(v1[n * 8 + g]);
                mma_tf32(oacc[n], aa, bb);
            }
        }
        __syncthreads();
    }

    const float inv0 = 1.f / l0, inv1 = 1.f / l1;
    const int r0 = q0 + mrow + g, r1 = r0 + 8;
#pragma unroll
    for (int n = 0; n < 8; ++n) {
        const int c = n * 8 + 2 * tg;
        *(half2*)(O + obase + (size_t)r0 * CDIM + c) =
            __floats2half2_rn(oacc[n][0] * inv0, oacc[n][1] * inv0);
        *(half2*)(O + obase + (size_t)r1 * CDIM + c) =
            __floats2half2_rn(oacc[n][2] * inv1, oacc[n][3] * inv1);
    }
}

// ---------------- launch ----------------
extern "C" void kernel_launch(void* const* d_in, const int* in_sizes, int n_in,
                              void* d_out, int out_size) {
    (void)in_sizes; (void)n_in; (void)out_size;
    const float* x    = (const float*)d_in[0];
    const float* Wq   = (const float*)d_in[1];
    const float* Wk   = (const float*)d_in[2];
    const float* Wv   = (const float*)d_in[3];
    const float* Wp   = (const float*)d_in[4];
    const float* bp   = (const float*)d_in[5];
    const float* ln1g = (const float*)d_in[6];
    const float* ln1b = (const float*)d_in[7];
    const float* ln2g = (const float*)d_in[8];
    const float* ln2b = (const float*)d_in[9];
    const float* W1   = (const float*)d_in[10];
    const float* b1   = (const float*)d_in[11];
    const float* W2   = (const float*)d_in[12];
    const float* b2   = (const float*)d_in[13];
    float* out = (float*)d_out;

    __half *h, *qkv, *attn, *ff, *wqkvT, *wpT, *w1T, *w2T;
    float *x1;
    cudaGetSymbolAddress((void**)&h,     g_h);
    cudaGetSymbolAddress((void**)&qkv,   g_qkv);
    cudaGetSymbolAddress((void**)&attn,  g_attn);
    cudaGetSymbolAddress((void**)&x1,    g_x1);
    cudaGetSymbolAddress((void**)&ff,    g_ff);
    cudaGetSymbolAddress((void**)&wqkvT, g_wqkvT);
    cudaGetSymbolAddress((void**)&wpT,   g_wpT);
    cudaGetSymbolAddress((void**)&w1T,   g_w1T);
    cudaGetSymbolAddress((void**)&w2T,   g_w2T);

    cudaFuncSetAttribute(h16gemm_kernel<0>, cudaFuncAttributeMaxDynamicSharedMemorySize, H_SMEM);
    cudaFuncSetAttribute(h16gemm_kernel<2>, cudaFuncAttributeMaxDynamicSharedMemorySize, H_SMEM);
    cudaFuncSetAttribute(h16gemm_kernel<3>, cudaFuncAttributeMaxDynamicSharedMemorySize, H_SMEM);
    cudaFuncSetAttribute(flash_attn_tc_kernel, cudaFuncAttributeMaxDynamicSharedMemorySize, FA_SMEM);

    // 0) weight transposes (fp16, K-major)
    dim3 tb(32, 8);
    pack_wqkv_t_kernel<<<dim3(CDIM / 32, QKVDIM / 32), tb>>>(Wq, Wk, Wv);
    transpose_cvt_kernel<<<dim3(CDIM / 32, CDIM / 32), tb>>>(Wp, wpT, CDIM, CDIM);
    transpose_cvt_kernel<<<dim3(FDIM / 32, CDIM / 32), tb>>>(W1, w1T, CDIM, FDIM);
    transpose_cvt_kernel<<<dim3(CDIM / 32, FDIM / 32), tb>>>(W2, w2T, FDIM, CDIM);

    // 1) LN1
    layernorm_kernel<<<MROWS, 256>>>(x, ln1g, ln1b, h);

    // 2) fused QKV projection: [8192,1024] @ [1024,3072]
    h16gemm_kernel<0><<<dim3(QKVDIM / 128, MROWS / 128), 256, H_SMEM>>>(
        h, wqkvT, qkv, nullptr, nullptr, MROWS, QKVDIM, CDIM);

    // 3) attention
    flash_attn_tc_kernel<<<dim3(TSEQ / 64, NHEAD, BATCH), 128, FA_SMEM>>>(qkv, attn);

    // 4) output projection + residual: x1 = x + attn@Wp + bp
    h16gemm_kernel<3><<<dim3(CDIM / 128, MROWS / 128), 256, H_SMEM>>>(
        attn, wpT, x1, bp, x, MROWS, CDIM, CDIM);

    // 5) LN2
    layernorm_kernel<<<MROWS, 256>>>(x1, ln2g, ln2b, h);

    // 6) ff = relu(h@W1 + b1)
    h16gemm_kernel<2><<<dim3(FDIM / 128, MROWS / 128), 256, H_SMEM>>>(
        h, w1T, ff, b1, nullptr, MROWS, FDIM, CDIM);

    // 7) out = x1 + ff@W2 + b2
    h16gemm_kernel<3><<<dim3(CDIM / 128, MROWS / 128), 256, H_SMEM>>>(
        ff, w2T, out, b2, x1, MROWS, CDIM, FDIM);
}

// round 9
// speedup vs baseline: 1.6277x; 1.0603x over previous
#include <cuda_runtime.h>
#include <cuda_fp16.h>
#include <cstdint>

// Problem constants
#define BATCH   4
#define TSEQ    2048
#define CDIM    1024
#define NHEAD   16
#define HDIM    64
#define FDIM    4096
#define MROWS   (BATCH * TSEQ)          // 8192
#define QKVDIM  (3 * CDIM)              // 3072
#define SM_SCALE 0.03125f               // C^-0.5 = 1/32

// ---------------- scratch (static device globals; no allocation) ----------------
__device__ __half g_h    [MROWS * CDIM];    // LN output
__device__ __half g_qkv  [MROWS * QKVDIM];  // q | k | v
__device__ __half g_attn [MROWS * CDIM];    // attention out
__device__ float  g_x1   [MROWS * CDIM];    // x + attn@Wp + bp (fp32 residual)
__device__ __half g_ff   [MROWS * FDIM];    // relu(h@W1+b1)
__device__ __half g_wqkvT[QKVDIM * CDIM];   // [3C, C] K-major
__device__ __half g_wpT  [CDIM * CDIM];     // Wp^T [C, C]
__device__ __half g_w1T  [FDIM * CDIM];     // W1^T [4C, C]
__device__ __half g_w2T  [CDIM * FDIM];     // W2^T [C, 4C]

// ---------------- helpers ----------------
__device__ __forceinline__ uint32_t smem_u32(const void* p) {
    return (uint32_t)__cvta_generic_to_shared(p);
}
__device__ __forceinline__ void cp16s(uint32_t saddr, const void* gsrc) {
    asm volatile("cp.async.cg.shared.global [%0], [%1], 16;\n" :: "r"(saddr), "l"(gsrc));
}
__device__ __forceinline__ uint32_t lds32(const __half* p) {
    return *(const uint32_t*)p;
}
// fp16 mma: D(f32) += A(f16) B(f16), m16n8k16, row.col
__device__ __forceinline__ void mma_f16(float* c, const uint32_t* a, const uint32_t* b) {
    asm volatile(
        "mma.sync.aligned.m16n8k16.row.col.f32.f16.f16.f32 "
        "{%0,%1,%2,%3}, {%4,%5,%6,%7}, {%8,%9}, {%0,%1,%2,%3};\n"
        : "+f"(c[0]), "+f"(c[1]), "+f"(c[2]), "+f"(c[3])
        : "r"(a[0]), "r"(a[1]), "r"(a[2]), "r"(a[3]), "r"(b[0]), "r"(b[1]));
}

// ---------------- weight transposes (fp16 out, K-major) ----------------
__global__ void pack_wqkv_t_kernel(const float* __restrict__ Wq, const float* __restrict__ Wk,
                                   const float* __restrict__ Wv) {
    __shared__ float s[32][33];
    const int c0 = blockIdx.x * 32;
    const int n0 = blockIdx.y * 32;
    const float* W = (n0 < CDIM) ? Wq : (n0 < 2 * CDIM ? Wk : Wv);
    const int nloc = n0 & (CDIM - 1);
    const int h = nloc >> 6, d0 = nloc & 63;
    const int tx = threadIdx.x, ty = threadIdx.y;
#pragma unroll
    for (int i = ty; i < 32; i += 8)
        s[i][tx] = W[h * (CDIM * HDIM) + (c0 + i) * HDIM + d0 + tx];
    __syncthreads();
#pragma unroll
    for (int i = ty; i < 32; i += 8)
        g_wqkvT[(size_t)(n0 + i) * CDIM + c0 + tx] = __float2half_rn(s[tx][i]);
}

__global__ void transpose_cvt_kernel(const float* __restrict__ src, __half* __restrict__ dst,
                                     int R, int Cc) {
    __shared__ float s[32][33];
    const int c0 = blockIdx.x * 32, r0 = blockIdx.y * 32;
    const int tx = threadIdx.x, ty = threadIdx.y;
#pragma unroll
    for (int i = ty; i < 32; i += 8)
        s[i][tx] = src[(size_t)(r0 + i) * Cc + c0 + tx];
    __syncthreads();
#pragma unroll
    for (int i = ty; i < 32; i += 8)
        dst[(size_t)(c0 + i) * R + r0 + tx] = __float2half_rn(s[tx][i]);
}

// ---------------- layernorm (fp16 output) ----------------
__global__ void layernorm_kernel(const float* __restrict__ x, const float* __restrict__ g,
                                 const float* __restrict__ b, __half* __restrict__ out) {
    const int row = blockIdx.x;
    const int t = threadIdx.x;
    const size_t off = (size_t)row * CDIM + t * 4;
    float4 v = *(const float4*)(x + off);
    float s  = v.x + v.y + v.z + v.w;
    float ss = fmaf(v.x, v.x, fmaf(v.y, v.y, fmaf(v.z, v.z, v.w * v.w)));
#pragma unroll
    for (int o = 16; o; o >>= 1) {
        s  += __shfl_xor_sync(0xffffffffu, s,  o);
        ss += __shfl_xor_sync(0xffffffffu, ss, o);
    }
    __shared__ float ws[8], wss[8];
    __shared__ float s_mu, s_rs;
    int lane = t & 31, wid = t >> 5;
    if (lane == 0) { ws[wid] = s; wss[wid] = ss; }
    __syncthreads();
    if (t == 0) {
        float S = 0.f, SS = 0.f;
#pragma unroll
        for (int i = 0; i < 8; ++i) { S += ws[i]; SS += wss[i]; }
        float mu  = S * (1.f / CDIM);
        float var = SS * (1.f / CDIM) - mu * mu;
        s_mu = mu;
        s_rs = rsqrtf(var + 1e-5f);
    }
    __syncthreads();
    float mu = s_mu, rs = s_rs;
    float4 gv = *(const float4*)(g + t * 4);
    float4 bv = *(const float4*)(b + t * 4);
    *(half2*)(out + off)     = __floats2half2_rn((v.x - mu) * rs * gv.x + bv.x,
                                                 (v.y - mu) * rs * gv.y + bv.y);
    *(half2*)(out + off + 2) = __floats2half2_rn((v.z - mu) * rs * gv.z + bv.z,
                                                 (v.w - mu) * rs * gv.w + bv.w);
}

// ---------------- fp16 tensor-core GEMM ----------------
#define HBK   32
#define HSTR  40
#define HROWS 128
#define STAGE_H (2 * HROWS * HSTR)
#define H_SMEM  (3 * STAGE_H * 2)

template <int EPI>
__global__ __launch_bounds__(256, 2)
void h16gemm_kernel(const __half* __restrict__ A, const __half* __restrict__ Bt,
                    void* __restrict__ Cv, const float* __restrict__ bias,
                    const float* __restrict__ res, int M, int N, int K) {
    extern __shared__ __half hsm[];
    const uint32_t sb = smem_u32(hsm);
    const int tid  = threadIdx.x;
    const int lane = tid & 31, wid = tid >> 5;
    const int warpM = wid & 1;
    const int warpN = wid >> 1;
    const int row0 = blockIdx.y * 128, col0 = blockIdx.x * 128;
    const int g  = lane >> 2;
    const int tg = lane & 3;
    const int KT = K / HBK;

    float acc[4][4][4];
#pragma unroll
    for (int mt = 0; mt < 4; ++mt)
#pragma unroll
        for (int nt = 0; nt < 4; ++nt)
#pragma unroll
            for (int r = 0; r < 4; ++r) acc[mt][nt][r] = 0.f;

    auto load_tile = [&](int kt, int st) {
        const uint32_t aoff = st * STAGE_H;
        const uint32_t boff = aoff + HROWS * HSTR;
        const size_t gk = (size_t)kt * HBK;
#pragma unroll
        for (int i = 0; i < 2; ++i) {
            int ch = tid + i * 256;
            int r = ch >> 2, c8 = (ch & 3) * 8;
            cp16s(sb + (aoff + r * HSTR + c8) * 2, A  + (size_t)(row0 + r) * K + gk + c8);
            cp16s(sb + (boff + r * HSTR + c8) * 2, Bt + (size_t)(col0 + r) * K + gk + c8);
        }
    };

    load_tile(0, 0);
    asm volatile("cp.async.commit_group;\n");
    load_tile(1, 1);
    asm volatile("cp.async.commit_group;\n");

    for (int t = 0; t < KT; ++t) {
        if (t + 2 < KT) {
            load_tile(t + 2, (t + 2) % 3);
            asm volatile("cp.async.commit_group;\n");
            asm volatile("cp.async.wait_group 2;\n");
        } else {
            asm volatile("cp.async.wait_group 0;\n");
        }
        __syncthreads();

        const __half* as = hsm + (t % 3) * STAGE_H;
        const __half* bs = as + HROWS * HSTR;
#pragma unroll
        for (int kc = 0; kc < 2; ++kc) {
            const int ko = kc * 16 + 2 * tg;
            uint32_t a[4][4], b[4][2];
#pragma unroll
            for (int mt = 0; mt < 4; ++mt) {
                const int r = warpM * 64 + mt * 16 + g;
                a[mt][0] = lds32(as + r * HSTR + ko);
                a[mt][1] = lds32(as + (r + 8) * HSTR + ko);
                a[mt][2] = lds32(as + r * HSTR + ko + 8);
                a[mt][3] = lds32(as + (r + 8) * HSTR + ko + 8);
            }
#pragma unroll
            for (int nt = 0; nt < 4; ++nt) {
                const int n = warpN * 32 + nt * 8 + g;
                b[nt][0] = lds32(bs + n * HSTR + ko);
                b[nt][1] = lds32(bs + n * HSTR + ko + 8);
            }
#pragma unroll
            for (int mt = 0; mt < 4; ++mt)
#pragma unroll
                for (int nt = 0; nt < 4; ++nt)
                    mma_f16(acc[mt][nt], a[mt], b[nt]);
        }
        __syncthreads();
    }

#pragma unroll
    for (int mt = 0; mt < 4; ++mt) {
#pragma unroll
        for (int nt = 0; nt < 4; ++nt) {
            const int r = row0 + warpM * 64 + mt * 16 + g;
            const int c = col0 + warpN * 32 + nt * 8 + 2 * tg;
            float2 v0 = make_float2(acc[mt][nt][0], acc[mt][nt][1]);
            float2 v1 = make_float2(acc[mt][nt][2], acc[mt][nt][3]);
            if (EPI >= 2) {
                float b0 = bias[c], b1 = bias[c + 1];
                v0.x += b0; v0.y += b1;
                v1.x += b0; v1.y += b1;
            }
            if (EPI == 2) {
                v0.x = fmaxf(v0.x, 0.f); v0.y = fmaxf(v0.y, 0.f);
                v1.x = fmaxf(v1.x, 0.f); v1.y = fmaxf(v1.y, 0.f);
            }
            if (EPI == 3) {
                float2 r0 = *(const float2*)(res + (size_t)r * N + c);
                float2 r1 = *(const float2*)(res + (size_t)(r + 8) * N + c);
                v0.x += r0.x; v0.y += r0.y;
                v1.x += r1.x; v1.y += r1.y;
                float* Cf = (float*)Cv;
                *(float2*)(Cf + (size_t)r * N + c)       = v0;
                *(float2*)(Cf + (size_t)(r + 8) * N + c) = v1;
            } else {
                __half* Ch = (__half*)Cv;
                *(half2*)(Ch + (size_t)r * N + c)       = __floats2half2_rn(v0.x, v0.y);
                *(half2*)(Ch + (size_t)(r + 8) * N + c) = __floats2half2_rn(v1.x, v1.y);
            }
        }
    }
}

// ---------------- fp16 flash attention, causal, register-resident P ----------------
// 64 q-rows x 64 keys per tile; 4 warps; warp owns 16 q-rows.
// Ks: [64 s][72 d] half (cp.async). Vt: [64 d][72 s] half, s index XOR-swizzled by
// f(d) = 2*(d>>3): transpose stores reduced to 2-way conflicts; B-frag loads
// (f constant within an n-block) stay conflict-free.
#define KS2 72
#define VT2 72

__global__ __launch_bounds__(128)
void flash_attn_h_kernel(const __half* __restrict__ QKV, __half* __restrict__ O) {
    __shared__ __half Ks[64 * KS2];
    __shared__ __half Vt[64 * VT2];

    const int qb = blockIdx.x, h = blockIdx.y, b = blockIdx.z;
    const int tid = threadIdx.x, lane = tid & 31, w = tid >> 5;
    const int g = lane >> 2, tg = lane & 3;
    const int q0 = qb * 64;
    const int mrow = w * 16;
    const size_t base  = (size_t)b * TSEQ * QKVDIM + h * HDIM;
    const size_t obase = (size_t)b * TSEQ * CDIM + h * HDIM;
    const __half* Q = QKV;
    const __half* K = QKV + CDIM;
    const __half* V = QKV + 2 * CDIM;
    const uint32_t ks_sb = smem_u32(Ks);

    // ---- stage Q into Ks buffer once, extract fragments ----
    for (int i = tid; i < 512; i += 128) {
        int r = i >> 3, c8 = (i & 7) * 8;
        *(uint4*)(Ks + r * KS2 + c8) =
            *(const uint4*)(Q + base + (size_t)(q0 + r) * QKVDIM + c8);
    }
    __syncthreads();
    uint32_t qf[4][4];
#pragma unroll
    for (int kc = 0; kc < 4; ++kc) {
        const int ko = kc * 16 + 2 * tg;
        qf[kc][0] = lds32(Ks + (mrow + g) * KS2 + ko);
        qf[kc][1] = lds32(Ks + (mrow + g + 8) * KS2 + ko);
        qf[kc][2] = lds32(Ks + (mrow + g) * KS2 + ko + 8);
        qf[kc][3] = lds32(Ks + (mrow + g + 8) * KS2 + ko + 8);
    }
    __syncthreads();

    float oacc[8][4];
#pragma unroll
    for (int n = 0; n < 8; ++n)
#pragma unroll
        for (int r = 0; r < 4; ++r) oacc[n][r] = 0.f;
    float m0 = -1e30f, m1 = -1e30f, l0 = 0.f, l1 = 0.f;

    for (int j = 0; j <= qb; ++j) {
        const int k0 = j * 64;
        // K tile via cp.async (row stride 144B = 9x16B, aligned)
#pragma unroll
        for (int i = 0; i < 4; ++i) {
            int ch = tid + i * 128;
            int r = ch >> 3, c8 = (ch & 7) * 8;
            cp16s(ks_sb + (r * KS2 + c8) * 2,
                  K + base + (size_t)(k0 + r) * QKVDIM + c8);
        }
        // V tile: transpose into Vt with XOR swizzle on s
        for (int i = tid; i < 512; i += 128) {
            int s = i >> 3, c8 = (i & 7) * 8;
            uint4 u = *(const uint4*)(V + base + (size_t)(k0 + s) * QKVDIM + c8);
            const __half* hv = (const __half*)&u;
#pragma unroll
            for (int d = 0; d < 8; ++d) {
                int dd = c8 + d;
                Vt[dd * VT2 + (s ^ (2 * (dd >> 3)))] = hv[d];
            }
        }
        asm volatile("cp.async.commit_group;\n");
        asm volatile("cp.async.wait_group 0;\n");
        __syncthreads();

        // ---- S = Q K^T : 8 n-blocks x 4 k-chunks ----
        float sacc[8][4];
#pragma unroll
        for (int n = 0; n < 8; ++n)
#pragma unroll
            for (int r = 0; r < 4; ++r) sacc[n][r] = 0.f;
#pragma unroll
        for (int nb = 0; nb < 8; ++nb) {
            const __half* krow = Ks + (nb * 8 + g) * KS2;
#pragma unroll
            for (int kc = 0; kc < 4; ++kc) {
                uint32_t bb[2];
                const int ko = kc * 16 + 2 * tg;
                bb[0] = lds32(krow + ko);
                bb[1] = lds32(krow + ko + 8);
                mma_f16(sacc[nb], qf[kc], bb);
            }
        }

        // ---- online softmax (fp32) ----
        const bool diag = (j == qb);
#pragma unroll
        for (int nb = 0; nb < 8; ++nb) {
            sacc[nb][0] *= SM_SCALE; sacc[nb][1] *= SM_SCALE;
            sacc[nb][2] *= SM_SCALE; sacc[nb][3] *= SM_SCALE;
            if (diag) {
                const int c0 = nb * 8 + 2 * tg, c1 = c0 + 1;
                const int r0 = mrow + g, r1 = r0 + 8;
                if (c0 > r0) sacc[nb][0] = -1e30f;
                if (c1 > r0) sacc[nb][1] = -1e30f;
                if (c0 > r1) sacc[nb][2] = -1e30f;
                if (c1 > r1) sacc[nb][3] = -1e30f;
            }
        }
        float mx0 = -1e30f, mx1 = -1e30f;
#pragma unroll
        for (int nb = 0; nb < 8; ++nb) {
            mx0 = fmaxf(mx0, fmaxf(sacc[nb][0], sacc[nb][1]));
            mx1 = fmaxf(mx1, fmaxf(sacc[nb][2], sacc[nb][3]));
        }
        mx0 = fmaxf(mx0, __shfl_xor_sync(0xffffffffu, mx0, 1));
        mx0 = fmaxf(mx0, __shfl_xor_sync(0xffffffffu, mx0, 2));
        mx1 = fmaxf(mx1, __shfl_xor_sync(0xffffffffu, mx1, 1));
        mx1 = fmaxf(mx1, __shfl_xor_sync(0xffffffffu, mx1, 2));
        const float mn0 = fmaxf(m0, mx0), mn1 = fmaxf(m1, mx1);
        const float al0 = __expf(m0 - mn0), al1 = __expf(m1 - mn1);
        m0 = mn0; m1 = mn1;

        float sum0 = 0.f, sum1 = 0.f;
#pragma unroll
        for (int nb = 0; nb < 8; ++nb) {
            sacc[nb][0] = __expf(sacc[nb][0] - mn0);
            sacc[nb][1] = __expf(sacc[nb][1] - mn0);
            sacc[nb][2] = __expf(sacc[nb][2] - mn1);
            sacc[nb][3] = __expf(sacc[nb][3] - mn1);
            sum0 += sacc[nb][0] + sacc[nb][1];
            sum1 += sacc[nb][2] + sacc[nb][3];
        }
        sum0 += __shfl_xor_sync(0xffffffffu, sum0, 1);
        sum0 += __shfl_xor_sync(0xffffffffu, sum0, 2);
        sum1 += __shfl_xor_sync(0xffffffffu, sum1, 1);
        sum1 += __shfl_xor_sync(0xffffffffu, sum1, 2);
        l0 = l0 * al0 + sum0;
        l1 = l1 * al1 + sum1;
#pragma unroll
        for (int nb = 0; nb < 8; ++nb) {
            oacc[nb][0] *= al0; oacc[nb][1] *= al0;
            oacc[nb][2] *= al1; oacc[nb][3] *= al1;
        }

        // ---- O += P V : P stays in registers as A-fragments ----
        // sacc[2kc..2kc+1] cover key slots kc*16..kc*16+15 for this thread's
        // (g, tg) position: exactly the m16n8k16 A-fragment layout.
#pragma unroll
        for (int kc = 0; kc < 4; ++kc) {
            uint32_t a[4];
            half2 h0 = __floats2half2_rn(sacc[2 * kc][0],     sacc[2 * kc][1]);
            half2 h1 = __floats2half2_rn(sacc[2 * kc][2],     sacc[2 * kc][3]);
            half2 h2 = __floats2half2_rn(sacc[2 * kc + 1][0], sacc[2 * kc + 1][1]);
            half2 h3 = __floats2half2_rn(sacc[2 * kc + 1][2], sacc[2 * kc + 1][3]);
            a[0] = *(uint32_t*)&h0;
            a[1] = *(uint32_t*)&h1;
            a[2] = *(uint32_t*)&h2;
            a[3] = *(uint32_t*)&h3;
#pragma unroll
            for (int nb = 0; nb < 8; ++nb) {
                const int f = 2 * nb;                 // = 2*((nb*8+g)>>3)
                const __half* vrow = Vt + (nb * 8 + g) * VT2;
                uint32_t bb[2];
                bb[0] = lds32(vrow + ((kc * 16 + 2 * tg) ^ f));
                bb[1] = lds32(vrow + ((kc * 16 + 8 + 2 * tg) ^ f));
                mma_f16(oacc[nb], a, bb);
            }
        }
        __syncthreads();
    }

    const float inv0 = 1.f / l0, inv1 = 1.f / l1;
    const int r0 = q0 + mrow + g, r1 = r0 + 8;
#pragma unroll
    for (int nb = 0; nb < 8; ++nb) {
        const int c = nb * 8 + 2 * tg;
        *(half2*)(O + obase + (size_t)r0 * CDIM + c) =
            __floats2half2_rn(oacc[nb][0] * inv0, oacc[nb][1] * inv0);
        *(half2*)(O + obase + (size_t)r1 * CDIM + c) =
            __floats2half2_rn(oacc[nb][2] * inv1, oacc[nb][3] * inv1);
    }
}

// ---------------- launch ----------------
extern "C" void kernel_launch(void* const* d_in, const int* in_sizes, int n_in,
                              void* d_out, int out_size) {
    (void)in_sizes; (void)n_in; (void)out_size;
    const float* x    = (const float*)d_in[0];
    const float* Wq   = (const float*)d_in[1];
    const float* Wk   = (const float*)d_in[2];
    const float* Wv   = (const float*)d_in[3];
    const float* Wp   = (const float*)d_in[4];
    const float* bp   = (const float*)d_in[5];
    const float* ln1g = (const float*)d_in[6];
    const float* ln1b = (const float*)d_in[7];
    const float* ln2g = (const float*)d_in[8];
    const float* ln2b = (const float*)d_in[9];
    const float* W1   = (const float*)d_in[10];
    const float* b1   = (const float*)d_in[11];
    const float* W2   = (const float*)d_in[12];
    const float* b2   = (const float*)d_in[13];
    float* out = (float*)d_out;

    __half *h, *qkv, *attn, *ff, *wqkvT, *wpT, *w1T, *w2T;
    float *x1;
    cudaGetSymbolAddress((void**)&h,     g_h);
    cudaGetSymbolAddress((void**)&qkv,   g_qkv);
    cudaGetSymbolAddress((void**)&attn,  g_attn);
    cudaGetSymbolAddress((void**)&x1,    g_x1);
    cudaGetSymbolAddress((void**)&ff,    g_ff);
    cudaGetSymbolAddress((void**)&wqkvT, g_wqkvT);
    cudaGetSymbolAddress((void**)&wpT,   g_wpT);
    cudaGetSymbolAddress((void**)&w1T,   g_w1T);
    cudaGetSymbolAddress((void**)&w2T,   g_w2T);

    cudaFuncSetAttribute(h16gemm_kernel<0>, cudaFuncAttributeMaxDynamicSharedMemorySize, H_SMEM);
    cudaFuncSetAttribute(h16gemm_kernel<2>, cudaFuncAttributeMaxDynamicSharedMemorySize, H_SMEM);
    cudaFuncSetAttribute(h16gemm_kernel<3>, cudaFuncAttributeMaxDynamicSharedMemorySize, H_SMEM);

    // 0) weight transposes (fp16, K-major)
    dim3 tb(32, 8);
    pack_wqkv_t_kernel<<<dim3(CDIM / 32, QKVDIM / 32), tb>>>(Wq, Wk, Wv);
    transpose_cvt_kernel<<<dim3(CDIM / 32, CDIM / 32), tb>>>(Wp, wpT, CDIM, CDIM);
    transpose_cvt_kernel<<<dim3(FDIM / 32, CDIM / 32), tb>>>(W1, w1T, CDIM, FDIM);
    transpose_cvt_kernel<<<dim3(CDIM / 32, FDIM / 32), tb>>>(W2, w2T, FDIM, CDIM);

    // 1) LN1
    layernorm_kernel<<<MROWS, 256>>>(x, ln1g, ln1b, h);

    // 2) fused QKV projection
    h16gemm_kernel<0><<<dim3(QKVDIM / 128, MROWS / 128), 256, H_SMEM>>>(
        h, wqkvT, qkv, nullptr, nullptr, MROWS, QKVDIM, CDIM);

    // 3) attention (fp16 mma, register-resident P)
    flash_attn_h_kernel<<<dim3(TSEQ / 64, NHEAD, BATCH), 128>>>(qkv, attn);

    // 4) output projection + residual
    h16gemm_kernel<3><<<dim3(CDIM / 128, MROWS / 128), 256, H_SMEM>>>(
        attn, wpT, x1, bp, x, MROWS, CDIM, CDIM);

    // 5) LN2
    layernorm_kernel<<<MROWS, 256>>>(x1, ln2g, ln2b, h);

    // 6) ff = relu(h@W1 + b1)
    h16gemm_kernel<2><<<dim3(FDIM / 128, MROWS / 128), 256, H_SMEM>>>(
        h, w1T, ff, b1, nullptr, MROWS, FDIM, CDIM);

    // 7) out = x1 + ff@W2 + b2
    h16gemm_kernel<3><<<dim3(CDIM / 128, MROWS / 128), 256, H_SMEM>>>(
        ff, w2T, out, b2, x1, MROWS, CDIM, FDIM);
}

// round 10
// speedup vs baseline: 1.8133x; 1.1140x over previous
#include <cuda_runtime.h>
#include <cuda_fp16.h>
#include <cstdint>

// Problem constants
#define BATCH   4
#define TSEQ    2048
#define CDIM    1024
#define NHEAD   16
#define HDIM    64
#define FDIM    4096
#define MROWS   (BATCH * TSEQ)          // 8192
#define QKVDIM  (3 * CDIM)              // 3072
#define SM_SCALE 0.03125f               // C^-0.5 = 1/32

// ---------------- scratch (static device globals; no allocation) ----------------
__device__ __half g_h    [MROWS * CDIM];    // LN output
__device__ __half g_qkv  [MROWS * QKVDIM];  // q | k | v
__device__ __half g_attn [MROWS * CDIM];    // attention out
__device__ float  g_x1   [MROWS * CDIM];    // x + attn@Wp + bp (fp32 residual)
__device__ __half g_ff   [MROWS * FDIM];    // relu(h@W1+b1)
__device__ __half g_wqkvT[QKVDIM * CDIM];   // [3C, C] K-major
__device__ __half g_wpT  [CDIM * CDIM];     // Wp^T [C, C]
__device__ __half g_w1T  [FDIM * CDIM];     // W1^T [4C, C]
__device__ __half g_w2T  [CDIM * FDIM];     // W2^T [C, 4C]

// ---------------- helpers ----------------
__device__ __forceinline__ uint32_t smem_u32(const void* p) {
    return (uint32_t)__cvta_generic_to_shared(p);
}
__device__ __forceinline__ void cp16s(uint32_t saddr, const void* gsrc) {
    asm volatile("cp.async.cg.shared.global [%0], [%1], 16;\n" :: "r"(saddr), "l"(gsrc));
}
__device__ __forceinline__ uint32_t lds32(const __half* p) {
    return *(const uint32_t*)p;
}
__device__ __forceinline__ void ldmx2_trans(uint32_t& r0, uint32_t& r1, uint32_t saddr) {
    asm volatile("ldmatrix.sync.aligned.m8n8.x2.trans.shared.b16 {%0, %1}, [%2];"
                 : "=r"(r0), "=r"(r1) : "r"(saddr));
}
// fp16 mma: D(f32) += A(f16) B(f16), m16n8k16, row.col
__device__ __forceinline__ void mma_f16(float* c, const uint32_t* a, const uint32_t* b) {
    asm volatile(
        "mma.sync.aligned.m16n8k16.row.col.f32.f16.f16.f32 "
        "{%0,%1,%2,%3}, {%4,%5,%6,%7}, {%8,%9}, {%0,%1,%2,%3};\n"
        : "+f"(c[0]), "+f"(c[1]), "+f"(c[2]), "+f"(c[3])
        : "r"(a[0]), "r"(a[1]), "r"(a[2]), "r"(a[3]), "r"(b[0]), "r"(b[1]));
}

// ---------------- weight transposes (fp16 out, K-major) ----------------
__global__ void pack_wqkv_t_kernel(const float* __restrict__ Wq, const float* __restrict__ Wk,
                                   const float* __restrict__ Wv) {
    __shared__ float s[32][33];
    const int c0 = blockIdx.x * 32;
    const int n0 = blockIdx.y * 32;
    const float* W = (n0 < CDIM) ? Wq : (n0 < 2 * CDIM ? Wk : Wv);
    const int nloc = n0 & (CDIM - 1);
    const int h = nloc >> 6, d0 = nloc & 63;
    const int tx = threadIdx.x, ty = threadIdx.y;
#pragma unroll
    for (int i = ty; i < 32; i += 8)
        s[i][tx] = W[h * (CDIM * HDIM) + (c0 + i) * HDIM + d0 + tx];
    __syncthreads();
#pragma unroll
    for (int i = ty; i < 32; i += 8)
        g_wqkvT[(size_t)(n0 + i) * CDIM + c0 + tx] = __float2half_rn(s[tx][i]);
}

__global__ void transpose_cvt_kernel(const float* __restrict__ src, __half* __restrict__ dst,
                                     int R, int Cc) {
    __shared__ float s[32][33];
    const int c0 = blockIdx.x * 32, r0 = blockIdx.y * 32;
    const int tx = threadIdx.x, ty = threadIdx.y;
#pragma unroll
    for (int i = ty; i < 32; i += 8)
        s[i][tx] = src[(size_t)(r0 + i) * Cc + c0 + tx];
    __syncthreads();
#pragma unroll
    for (int i = ty; i < 32; i += 8)
        dst[(size_t)(c0 + i) * R + r0 + tx] = __float2half_rn(s[tx][i]);
}

// ---------------- layernorm (fp16 output) ----------------
__global__ void layernorm_kernel(const float* __restrict__ x, const float* __restrict__ g,
                                 const float* __restrict__ b, __half* __restrict__ out) {
    const int row = blockIdx.x;
    const int t = threadIdx.x;
    const size_t off = (size_t)row * CDIM + t * 4;
    float4 v = *(const float4*)(x + off);
    float s  = v.x + v.y + v.z + v.w;
    float ss = fmaf(v.x, v.x, fmaf(v.y, v.y, fmaf(v.z, v.z, v.w * v.w)));
#pragma unroll
    for (int o = 16; o; o >>= 1) {
        s  += __shfl_xor_sync(0xffffffffu, s,  o);
        ss += __shfl_xor_sync(0xffffffffu, ss, o);
    }
    __shared__ float ws[8], wss[8];
    __shared__ float s_mu, s_rs;
    int lane = t & 31, wid = t >> 5;
    if (lane == 0) { ws[wid] = s; wss[wid] = ss; }
    __syncthreads();
    if (t == 0) {
        float S = 0.f, SS = 0.f;
#pragma unroll
        for (int i = 0; i < 8; ++i) { S += ws[i]; SS += wss[i]; }
        float mu  = S * (1.f / CDIM);
        float var = SS * (1.f / CDIM) - mu * mu;
        s_mu = mu;
        s_rs = rsqrtf(var + 1e-5f);
    }
    __syncthreads();
    float mu = s_mu, rs = s_rs;
    float4 gv = *(const float4*)(g + t * 4);
    float4 bv = *(const float4*)(b + t * 4);
    *(half2*)(out + off)     = __floats2half2_rn((v.x - mu) * rs * gv.x + bv.x,
                                                 (v.y - mu) * rs * gv.y + bv.y);
    *(half2*)(out + off + 2) = __floats2half2_rn((v.z - mu) * rs * gv.z + bv.z,
                                                 (v.w - mu) * rs * gv.w + bv.w);
}

// ---------------- fp16 tensor-core GEMM (unchanged) ----------------
#define HBK   32
#define HSTR  40
#define HROWS 128
#define STAGE_H (2 * HROWS * HSTR)
#define H_SMEM  (3 * STAGE_H * 2)

template <int EPI>
__global__ __launch_bounds__(256, 2)
void h16gemm_kernel(const __half* __restrict__ A, const __half* __restrict__ Bt,
                    void* __restrict__ Cv, const float* __restrict__ bias,
                    const float* __restrict__ res, int M, int N, int K) {
    extern __shared__ __half hsm[];
    const uint32_t sb = smem_u32(hsm);
    const int tid  = threadIdx.x;
    const int lane = tid & 31, wid = tid >> 5;
    const int warpM = wid & 1;
    const int warpN = wid >> 1;
    const int row0 = blockIdx.y * 128, col0 = blockIdx.x * 128;
    const int g  = lane >> 2;
    const int tg = lane & 3;
    const int KT = K / HBK;

    float acc[4][4][4];
#pragma unroll
    for (int mt = 0; mt < 4; ++mt)
#pragma unroll
        for (int nt = 0; nt < 4; ++nt)
#pragma unroll
            for (int r = 0; r < 4; ++r) acc[mt][nt][r] = 0.f;

    auto load_tile = [&](int kt, int st) {
        const uint32_t aoff = st * STAGE_H;
        const uint32_t boff = aoff + HROWS * HSTR;
        const size_t gk = (size_t)kt * HBK;
#pragma unroll
        for (int i = 0; i < 2; ++i) {
            int ch = tid + i * 256;
            int r = ch >> 2, c8 = (ch & 3) * 8;
            cp16s(sb + (aoff + r * HSTR + c8) * 2, A  + (size_t)(row0 + r) * K + gk + c8);
            cp16s(sb + (boff + r * HSTR + c8) * 2, Bt + (size_t)(col0 + r) * K + gk + c8);
        }
    };

    load_tile(0, 0);
    asm volatile("cp.async.commit_group;\n");
    load_tile(1, 1);
    asm volatile("cp.async.commit_group;\n");

    for (int t = 0; t < KT; ++t) {
        if (t + 2 < KT) {
            load_tile(t + 2, (t + 2) % 3);
            asm volatile("cp.async.commit_group;\n");
            asm volatile("cp.async.wait_group 2;\n");
        } else {
            asm volatile("cp.async.wait_group 0;\n");
        }
        __syncthreads();

        const __half* as = hsm + (t % 3) * STAGE_H;
        const __half* bs = as + HROWS * HSTR;
#pragma unroll
        for (int kc = 0; kc < 2; ++kc) {
            const int ko = kc * 16 + 2 * tg;
            uint32_t a[4][4], b[4][2];
#pragma unroll
            for (int mt = 0; mt < 4; ++mt) {
                const int r = warpM * 64 + mt * 16 + g;
                a[mt][0] = lds32(as + r * HSTR + ko);
                a[mt][1] = lds32(as + (r + 8) * HSTR + ko);
                a[mt][2] = lds32(as + r * HSTR + ko + 8);
                a[mt][3] = lds32(as + (r + 8) * HSTR + ko + 8);
            }
#pragma unroll
            for (int nt = 0; nt < 4; ++nt) {
                const int n = warpN * 32 + nt * 8 + g;
                b[nt][0] = lds32(bs + n * HSTR + ko);
                b[nt][1] = lds32(bs + n * HSTR + ko + 8);
            }
#pragma unroll
            for (int mt = 0; mt < 4; ++mt)
#pragma unroll
                for (int nt = 0; nt < 4; ++nt)
                    mma_f16(acc[mt][nt], a[mt], b[nt]);
        }
        __syncthreads();
    }

#pragma unroll
    for (int mt = 0; mt < 4; ++mt) {
#pragma unroll
        for (int nt = 0; nt < 4; ++nt) {
            const int r = row0 + warpM * 64 + mt * 16 + g;
            const int c = col0 + warpN * 32 + nt * 8 + 2 * tg;
            float2 v0 = make_float2(acc[mt][nt][0], acc[mt][nt][1]);
            float2 v1 = make_float2(acc[mt][nt][2], acc[mt][nt][3]);
            if (EPI >= 2) {
                float b0 = bias[c], b1 = bias[c + 1];
                v0.x += b0; v0.y += b1;
                v1.x += b0; v1.y += b1;
            }
            if (EPI == 2) {
                v0.x = fmaxf(v0.x, 0.f); v0.y = fmaxf(v0.y, 0.f);
                v1.x = fmaxf(v1.x, 0.f); v1.y = fmaxf(v1.y, 0.f);
            }
            if (EPI == 3) {
                float2 r0 = *(const float2*)(res + (size_t)r * N + c);
                float2 r1 = *(const float2*)(res + (size_t)(r + 8) * N + c);
                v0.x += r0.x; v0.y += r0.y;
                v1.x += r1.x; v1.y += r1.y;
                float* Cf = (float*)Cv;
                *(float2*)(Cf + (size_t)r * N + c)       = v0;
                *(float2*)(Cf + (size_t)(r + 8) * N + c) = v1;
            } else {
                __half* Ch = (__half*)Cv;
                *(half2*)(Ch + (size_t)r * N + c)       = __floats2half2_rn(v0.x, v0.y);
                *(half2*)(Ch + (size_t)(r + 8) * N + c) = __floats2half2_rn(v1.x, v1.y);
            }
        }
    }
}

// ---------------- fp16 flash attention: double-buffered, ldmatrix.trans PV ----------------
// 64 q-rows x 64 keys per tile; 4 warps; warp owns 16 q-rows.
// Ks/Vs: [2 stages][64 s][72 d] half, both cp.async (row stride 144B = 9x16B).
// PV B-fragments come straight from Vs via ldmatrix.x2.trans (no manual transpose).
#define KS2 72
#define FA_TILE (64 * KS2)

__global__ __launch_bounds__(128)
void flash_attn_h_kernel(const __half* __restrict__ QKV, __half* __restrict__ O) {
    __shared__ __half Ks[2][FA_TILE];
    __shared__ __half Vs[2][FA_TILE];

    const int qb = blockIdx.x, h = blockIdx.y, b = blockIdx.z;
    const int tid = threadIdx.x, lane = tid & 31, w = tid >> 5;
    const int g = lane >> 2, tg = lane & 3;
    const int q0 = qb * 64;
    const int mrow = w * 16;
    const size_t base  = (size_t)b * TSEQ * QKVDIM + h * HDIM;
    const size_t obase = (size_t)b * TSEQ * CDIM + h * HDIM;
    const __half* Q = QKV;
    const __half* K = QKV + CDIM;
    const __half* V = QKV + 2 * CDIM;
    const uint32_t ks_sb = smem_u32(Ks);
    const uint32_t vs_sb = smem_u32(Vs);

    // ---- stage Q via Ks[0], extract fragments ----
    for (int i = tid; i < 512; i += 128) {
        int r = i >> 3, c8 = (i & 7) * 8;
        *(uint4*)(&Ks[0][r * KS2 + c8]) =
            *(const uint4*)(Q + base + (size_t)(q0 + r) * QKVDIM + c8);
    }
    __syncthreads();
    uint32_t qf[4][4];
#pragma unroll
    for (int kc = 0; kc < 4; ++kc) {
        const int ko = kc * 16 + 2 * tg;
        qf[kc][0] = lds32(&Ks[0][(mrow + g) * KS2 + ko]);
        qf[kc][1] = lds32(&Ks[0][(mrow + g + 8) * KS2 + ko]);
        qf[kc][2] = lds32(&Ks[0][(mrow + g) * KS2 + ko + 8]);
        qf[kc][3] = lds32(&Ks[0][(mrow + g + 8) * KS2 + ko + 8]);
    }
    __syncthreads();

    // tile loader: K+V tile j into stage st (one commit group by caller)
    auto issue_tile = [&](int j, int st) {
        const int k0 = j * 64;
        const uint32_t ko = st * FA_TILE * 2;
#pragma unroll
        for (int i = 0; i < 4; ++i) {
            int ch = tid + i * 128;
            int r = ch >> 3, c8 = (ch & 7) * 8;
            const size_t grow = base + (size_t)(k0 + r) * QKVDIM + c8;
            cp16s(ks_sb + ko + (r * KS2 + c8) * 2, K + grow);
            cp16s(vs_sb + ko + (r * KS2 + c8) * 2, V + grow);
        }
    };

    float oacc[8][4];
#pragma unroll
    for (int n = 0; n < 8; ++n)
#pragma unroll
        for (int r = 0; r < 4; ++r) oacc[n][r] = 0.f;
    float m0 = -1e30f, m1 = -1e30f, l0 = 0.f, l1 = 0.f;

    issue_tile(0, 0);
    asm volatile("cp.async.commit_group;\n");

    for (int j = 0; j <= qb; ++j) {
        const int st = j & 1;
        if (j < qb) {
            issue_tile(j + 1, st ^ 1);
            asm volatile("cp.async.commit_group;\n");
            asm volatile("cp.async.wait_group 1;\n");
        } else {
            asm volatile("cp.async.wait_group 0;\n");
        }
        __syncthreads();

        // ---- S = Q K^T : 8 n-blocks x 4 k-chunks ----
        float sacc[8][4];
#pragma unroll
        for (int n = 0; n < 8; ++n)
#pragma unroll
            for (int r = 0; r < 4; ++r) sacc[n][r] = 0.f;
#pragma unroll
        for (int nb = 0; nb < 8; ++nb) {
            const __half* krow = &Ks[st][(nb * 8 + g) * KS2];
#pragma unroll
            for (int kc = 0; kc < 4; ++kc) {
                uint32_t bb[2];
                const int ko = kc * 16 + 2 * tg;
                bb[0] = lds32(krow + ko);
                bb[1] = lds32(krow + ko + 8);
                mma_f16(sacc[nb], qf[kc], bb);
            }
        }

        // ---- online softmax (fp32) ----
        const bool diag = (j == qb);
#pragma unroll
        for (int nb = 0; nb < 8; ++nb) {
            sacc[nb][0] *= SM_SCALE; sacc[nb][1] *= SM_SCALE;
            sacc[nb][2] *= SM_SCALE; sacc[nb][3] *= SM_SCALE;
            if (diag) {
                const int c0 = nb * 8 + 2 * tg, c1 = c0 + 1;
                const int r0 = mrow + g, r1 = r0 + 8;
                if (c0 > r0) sacc[nb][0] = -1e30f;
                if (c1 > r0) sacc[nb][1] = -1e30f;
                if (c0 > r1) sacc[nb][2] = -1e30f;
                if (c1 > r1) sacc[nb][3] = -1e30f;
            }
        }
        float mx0 = -1e30f, mx1 = -1e30f;
#pragma unroll
        for (int nb = 0; nb < 8; ++nb) {
            mx0 = fmaxf(mx0, fmaxf(sacc[nb][0], sacc[nb][1]));
            mx1 = fmaxf(mx1, fmaxf(sacc[nb][2], sacc[nb][3]));
        }
        mx0 = fmaxf(mx0, __shfl_xor_sync(0xffffffffu, mx0, 1));
        mx0 = fmaxf(mx0, __shfl_xor_sync(0xffffffffu, mx0, 2));
        mx1 = fmaxf(mx1, __shfl_xor_sync(0xffffffffu, mx1, 1));
        mx1 = fmaxf(mx1, __shfl_xor_sync(0xffffffffu, mx1, 2));
        const float mn0 = fmaxf(m0, mx0), mn1 = fmaxf(m1, mx1);
        const float al0 = __expf(m0 - mn0), al1 = __expf(m1 - mn1);
        m0 = mn0; m1 = mn1;

        float sum0 = 0.f, sum1 = 0.f;
#pragma unroll
        for (int nb = 0; nb < 8; ++nb) {
            sacc[nb][0] = __expf(sacc[nb][0] - mn0);
            sacc[nb][1] = __expf(sacc[nb][1] - mn0);
            sacc[nb][2] = __expf(sacc[nb][2] - mn1);
            sacc[nb][3] = __expf(sacc[nb][3] - mn1);
            sum0 += sacc[nb][0] + sacc[nb][1];
            sum1 += sacc[nb][2] + sacc[nb][3];
        }
        sum0 += __shfl_xor_sync(0xffffffffu, sum0, 1);
        sum0 += __shfl_xor_sync(0xffffffffu, sum0, 2);
        sum1 += __shfl_xor_sync(0xffffffffu, sum1, 1);
        sum1 += __shfl_xor_sync(0xffffffffu, sum1, 2);
        l0 = l0 * al0 + sum0;
        l1 = l1 * al1 + sum1;
#pragma unroll
        for (int nb = 0; nb < 8; ++nb) {
            oacc[nb][0] *= al0; oacc[nb][1] *= al0;
            oacc[nb][2] *= al1; oacc[nb][3] *= al1;
        }

        // ---- O += P V : P in registers as A-frags, V B-frags via ldmatrix.trans ----
        const uint32_t vst = vs_sb + st * FA_TILE * 2;
        const int lrow = lane & 15;
#pragma unroll
        for (int kc = 0; kc < 4; ++kc) {
            uint32_t a[4];
            half2 h0 = __floats2half2_rn(sacc[2 * kc][0],     sacc[2 * kc][1]);
            half2 h1 = __floats2half2_rn(sacc[2 * kc][2],     sacc[2 * kc][3]);
            half2 h2 = __floats2half2_rn(sacc[2 * kc + 1][0], sacc[2 * kc + 1][1]);
            half2 h3 = __floats2half2_rn(sacc[2 * kc + 1][2], sacc[2 * kc + 1][3]);
            a[0] = *(uint32_t*)&h0;
            a[1] = *(uint32_t*)&h1;
            a[2] = *(uint32_t*)&h2;
            a[3] = *(uint32_t*)&h3;
            const uint32_t rowaddr = vst + ((kc * 16 + lrow) * KS2) * 2;
#pragma unroll
            for (int nb = 0; nb < 8; ++nb) {
                uint32_t bb[2];
                ldmx2_trans(bb[0], bb[1], rowaddr + nb * 16);
                mma_f16(oacc[nb], a, bb);
            }
        }
        __syncthreads();
    }

    const float inv0 = 1.f / l0, inv1 = 1.f / l1;
    const int r0 = q0 + mrow + g, r1 = r0 + 8;
#pragma unroll
    for (int nb = 0; nb < 8; ++nb) {
        const int c = nb * 8 + 2 * tg;
        *(half2*)(O + obase + (size_t)r0 * CDIM + c) =
            __floats2half2_rn(oacc[nb][0] * inv0, oacc[nb][1] * inv0);
        *(half2*)(O + obase + (size_t)r1 * CDIM + c) =
            __floats2half2_rn(oacc[nb][2] * inv1, oacc[nb][3] * inv1);
    }
}

// ---------------- launch ----------------
extern "C" void kernel_launch(void* const* d_in, const int* in_sizes, int n_in,
                              void* d_out, int out_size) {
    (void)in_sizes; (void)n_in; (void)out_size;
    const float* x    = (const float*)d_in[0];
    const float* Wq   = (const float*)d_in[1];
    const float* Wk   = (const float*)d_in[2];
    const float* Wv   = (const float*)d_in[3];
    const float* Wp   = (const float*)d_in[4];
    const float* bp   = (const float*)d_in[5];
    const float* ln1g = (const float*)d_in[6];
    const float* ln1b = (const float*)d_in[7];
    const float* ln2g = (const float*)d_in[8];
    const float* ln2b = (const float*)d_in[9];
    const float* W1   = (const float*)d_in[10];
    const float* b1   = (const float*)d_in[11];
    const float* W2   = (const float*)d_in[12];
    const float* b2   = (const float*)d_in[13];
    float* out = (float*)d_out;

    __half *h, *qkv, *attn, *ff, *wqkvT, *wpT, *w1T, *w2T;
    float *x1;
    cudaGetSymbolAddress((void**)&h,     g_h);
    cudaGetSymbolAddress((void**)&qkv,   g_qkv);
    cudaGetSymbolAddress((void**)&attn,  g_attn);
    cudaGetSymbolAddress((void**)&x1,    g_x1);
    cudaGetSymbolAddress((void**)&ff,    g_ff);
    cudaGetSymbolAddress((void**)&wqkvT, g_wqkvT);
    cudaGetSymbolAddress((void**)&wpT,   g_wpT);
    cudaGetSymbolAddress((void**)&w1T,   g_w1T);
    cudaGetSymbolAddress((void**)&w2T,   g_w2T);

    cudaFuncSetAttribute(h16gemm_kernel<0>, cudaFuncAttributeMaxDynamicSharedMemorySize, H_SMEM);
    cudaFuncSetAttribute(h16gemm_kernel<2>, cudaFuncAttributeMaxDynamicSharedMemorySize, H_SMEM);
    cudaFuncSetAttribute(h16gemm_kernel<3>, cudaFuncAttributeMaxDynamicSharedMemorySize, H_SMEM);

    // 0) weight transposes (fp16, K-major)
    dim3 tb(32, 8);
    pack_wqkv_t_kernel<<<dim3(CDIM / 32, QKVDIM / 32), tb>>>(Wq, Wk, Wv);
    transpose_cvt_kernel<<<dim3(CDIM / 32, CDIM / 32), tb>>>(Wp, wpT, CDIM, CDIM);
    transpose_cvt_kernel<<<dim3(FDIM / 32, CDIM / 32), tb>>>(W1, w1T, CDIM, FDIM);
    transpose_cvt_kernel<<<dim3(CDIM / 32, FDIM / 32), tb>>>(W2, w2T, FDIM, CDIM);

    // 1) LN1
    layernorm_kernel<<<MROWS, 256>>>(x, ln1g, ln1b, h);

    // 2) fused QKV projection
    h16gemm_kernel<0><<<dim3(QKVDIM / 128, MROWS / 128), 256, H_SMEM>>>(
        h, wqkvT, qkv, nullptr, nullptr, MROWS, QKVDIM, CDIM);

    // 3) attention (fp16 mma, double-buffered, ldmatrix.trans PV)
    flash_attn_h_kernel<<<dim3(TSEQ / 64, NHEAD, BATCH), 128>>>(qkv, attn);

    // 4) output projection + residual
    h16gemm_kernel<3><<<dim3(CDIM / 128, MROWS / 128), 256, H_SMEM>>>(
        attn, wpT, x1, bp, x, MROWS, CDIM, CDIM);

    // 5) LN2
    layernorm_kernel<<<MROWS, 256>>>(x1, ln2g, ln2b, h);

    // 6) ff = relu(h@W1 + b1)
    h16gemm_kernel<2><<<dim3(FDIM / 128, MROWS / 128), 256, H_SMEM>>>(
        h, w1T, ff, b1, nullptr, MROWS, FDIM, CDIM);

    // 7) out = x1 + ff@W2 + b2
    h16gemm_kernel<3><<<dim3(CDIM / 128, MROWS / 128), 256, H_SMEM>>>(
        ff, w2T, out, b2, x1, MROWS, CDIM, FDIM);
}